// round 1
// baseline (speedup 1.0000x reference)
#include <cuda_runtime.h>
#include <math.h>

// ---------------------------------------------------------------------------
// Problem constants (B=8, N=4096, C=256, NH=8, D=32, R=4, H=W=64, S=256)
// ---------------------------------------------------------------------------
#define EPS_LN  1e-5f
#define EPS_ATT 1e-6f

// ---------------------------------------------------------------------------
// Scratch (static device globals; no allocation allowed)
// ---------------------------------------------------------------------------
__device__ float g_wsrT[4096 * 256];        // conv weight as [k=rr*256+i][o]
__device__ float g_wqT [256 * 256];
__device__ float g_wkT [256 * 256];
__device__ float g_wvT [256 * 256];
__device__ float g_wmT [256 * 256];
__device__ float g_w1T [512 * 512];
__device__ float g_w2T [512 * 256];
__device__ float g_part[4 * 2048 * 256];    // conv split-K partials
__device__ float g_src [2048 * 256];        // LN'd subsampled tokens
__device__ float g_kmat[2048 * 256];        // elu(k)+1
__device__ float g_vmat[2048 * 256];        // v
__device__ float g_kv  [64 * 32 * 32];      // [b*8+h][d][v]
__device__ float g_ksum[64 * 32];           // [b*8+h][d]
__device__ float g_qmat[8 * 4096 * 256];    // elu(q)+1
__device__ float g_msg [8 * 4096 * 256];    // attention message
__device__ float g_msgn[8 * 4096 * 256];    // after wm + LN1
__device__ float g_hmid[8 * 4096 * 512];    // relu(mlp1)

// ---------------------------------------------------------------------------
// Weight repacking
// ---------------------------------------------------------------------------
// sr_w is OIHW [256][256][4][4]; produce wsrT[(rr*256+i)*256 + o]
__global__ void repack_srw(const float* __restrict__ w, float* __restrict__ wt) {
    int idx = blockIdx.x * blockDim.x + threadIdx.x;   // 65536 threads
    int o = idx & 255, i = idx >> 8;
    const float* p = w + ((size_t)(o * 256 + i)) * 16;
#pragma unroll
    for (int rr = 0; rr < 16; rr++)
        wt[((size_t)(rr * 256 + i)) * 256 + o] = p[rr];
}

// dst[k*O + o] = src[o*K + k]
__global__ void transpose_k(const float* __restrict__ src, float* __restrict__ dst,
                            int O, int K) {
    __shared__ float tile[32][33];
    int kb = blockIdx.x * 32, ob = blockIdx.y * 32;
    int x = threadIdx.x, y = threadIdx.y;   // block (32,8)
#pragma unroll
    for (int r = 0; r < 32; r += 8)
        tile[y + r][x] = src[(size_t)(ob + y + r) * K + kb + x];
    __syncthreads();
#pragma unroll
    for (int r = 0; r < 32; r += 8)
        dst[(size_t)(kb + y + r) * O + ob + x] = tile[x][y + r];
}

// ---------------------------------------------------------------------------
// Conv-as-GEMM with split-K=4. grid(128, 4), 256 thr.
// A[m][k] with m=b*256+s, k=rr*256+i -> x[(b*4096 + n(s,rr))*256 + i]
// ---------------------------------------------------------------------------
__global__ void conv_gemm(const float* __restrict__ x, const float* __restrict__ wt,
                          float* __restrict__ part) {
    __shared__ float As[16][16];
    __shared__ float Bs[16][256];
    int tid = threadIdx.x, tx = tid & 31, ty = tid >> 5;
    int mtile = blockIdx.x * 16;
    int ks = blockIdx.y;
    float acc[2][8];
#pragma unroll
    for (int i = 0; i < 2; i++)
#pragma unroll
        for (int j = 0; j < 8; j++) acc[i][j] = 0.f;

    int mm = tid >> 4, kk = tid & 15;
    int m = mtile + mm;
    int b = m >> 8, s = m & 255, sh = s >> 4, sw = s & 15;
    int bk = tid >> 4, bc = tid & 15;

    int kbeg = ks * 1024;
    for (int k0 = kbeg; k0 < kbeg + 1024; k0 += 16) {
        int rr = k0 >> 8, i0 = k0 & 255;
        int r1 = rr >> 2, r2 = rr & 3;
        int n = (sh * 4 + r1) * 64 + sw * 4 + r2;
        As[mm][kk] = x[((size_t)(b << 12) + n) * 256 + i0 + kk];
        const float* brow = wt + (size_t)(k0 + bk) * 256;
#pragma unroll
        for (int q = 0; q < 4; q++) {
            int c = (bc + q * 16) * 4;
            *(float4*)&Bs[bk][c] = *(const float4*)&brow[c];
        }
        __syncthreads();
#pragma unroll
        for (int k = 0; k < 16; k++) {
            float4 b0 = *(float4*)&Bs[k][tx * 8];
            float4 b1 = *(float4*)&Bs[k][tx * 8 + 4];
#pragma unroll
            for (int i = 0; i < 2; i++) {
                float a = As[ty * 2 + i][k];
                acc[i][0] += a * b0.x; acc[i][1] += a * b0.y;
                acc[i][2] += a * b0.z; acc[i][3] += a * b0.w;
                acc[i][4] += a * b1.x; acc[i][5] += a * b1.y;
                acc[i][6] += a * b1.z; acc[i][7] += a * b1.w;
            }
        }
        __syncthreads();
    }
    float* dst = part + ((size_t)ks * 2048 + mtile) * 256;
#pragma unroll
    for (int i = 0; i < 2; i++) {
        int r = ty * 2 + i;
        *(float4*)&dst[(size_t)r * 256 + tx * 8]     = make_float4(acc[i][0], acc[i][1], acc[i][2], acc[i][3]);
        *(float4*)&dst[(size_t)r * 256 + tx * 8 + 4] = make_float4(acc[i][4], acc[i][5], acc[i][6], acc[i][7]);
    }
}

// Reduce split-K partials + bias + LayerNorm -> src. grid 256 blocks, 256 thr.
__global__ void reduce_ln(const float* __restrict__ part, const float* __restrict__ bias,
                          const float* __restrict__ g, const float* __restrict__ bb,
                          float* __restrict__ out) {
    int lane = threadIdx.x & 31, w = threadIdx.x >> 5;
    int row = blockIdx.x * 8 + w;
    float v[8];
#pragma unroll
    for (int j = 0; j < 8; j++) {
        int c = lane + j * 32;
        float s = 0.f;
#pragma unroll
        for (int ks = 0; ks < 4; ks++)
            s += part[((size_t)ks * 2048 + row) * 256 + c];
        v[j] = s + bias[c];
    }
    float sum = 0.f;
#pragma unroll
    for (int j = 0; j < 8; j++) sum += v[j];
#pragma unroll
    for (int o = 16; o; o >>= 1) sum += __shfl_xor_sync(0xffffffffu, sum, o);
    float mean = sum * (1.f / 256.f);
    float ss = 0.f;
#pragma unroll
    for (int j = 0; j < 8; j++) { float d = v[j] - mean; ss += d * d; }
#pragma unroll
    for (int o = 16; o; o >>= 1) ss += __shfl_xor_sync(0xffffffffu, ss, o);
    float inv = rsqrtf(ss * (1.f / 256.f) + EPS_LN);
#pragma unroll
    for (int j = 0; j < 8; j++) {
        int c = lane + j * 32;
        out[(size_t)row * 256 + c] = (v[j] - mean) * inv * g[c] + bb[c];
    }
}

// ---------------------------------------------------------------------------
// Generic GEMM: C[M x 256-per-block] = A[M x K] * Bt[K x Ntot] with epilogues.
// BN=256 (full LN row per block), BK=16, 256 threads, thread tile RPT x 8.
// ---------------------------------------------------------------------------
#define EPI_PLAIN    0
#define EPI_ELU1     1
#define EPI_RELU     2
#define EPI_LN       3
#define EPI_LN_RESID 4

template <int RPT, int EPI, bool CONCAT>
__global__ __launch_bounds__(256, 2)
void gemm_bn256(const float* __restrict__ A0, const float* __restrict__ A1,
                const float* __restrict__ Bt, float* __restrict__ C,
                int K, int Ntot,
                const float* __restrict__ gamma, const float* __restrict__ beta,
                const float* __restrict__ resid) {
    constexpr int BM = RPT * 8;
    __shared__ float As[BM][16];
    __shared__ float Bs[16][256];
    int tid = threadIdx.x, tx = tid & 31, ty = tid >> 5;
    int mtile = blockIdx.x * BM;
    int ncol0 = blockIdx.y * 256;
    int lda = CONCAT ? 256 : K;

    float acc[RPT][8];
#pragma unroll
    for (int i = 0; i < RPT; i++)
#pragma unroll
        for (int j = 0; j < 8; j++) acc[i][j] = 0.f;

    for (int k0 = 0; k0 < K; k0 += 16) {
        // ---- load A tile ----
        if (RPT == 8) {
            int m = tid >> 2, kq = tid & 3;
            int kc = k0 + kq * 4;
            const float* ap;
            if (CONCAT)
                ap = (kc < 256) ? (A0 + (size_t)(mtile + m) * 256 + kc)
                                : (A1 + (size_t)(mtile + m) * 256 + (kc - 256));
            else
                ap = A0 + (size_t)(mtile + m) * lda + kc;
            float4 av = *(const float4*)ap;
            *(float4*)&As[m][kq * 4] = av;
        } else {
            int m = tid >> 4, kk = tid & 15;
            As[m][kk] = A0[(size_t)(mtile + m) * lda + k0 + kk];
        }
        // ---- load B tile ----
        {
            int bk = tid >> 4, bc = tid & 15;
            const float* brow = Bt + (size_t)(k0 + bk) * Ntot + ncol0;
#pragma unroll
            for (int q = 0; q < 4; q++) {
                int c = (bc + q * 16) * 4;
                *(float4*)&Bs[bk][c] = *(const float4*)&brow[c];
            }
        }
        __syncthreads();
#pragma unroll
        for (int k = 0; k < 16; k++) {
            float4 b0 = *(float4*)&Bs[k][tx * 8];
            float4 b1 = *(float4*)&Bs[k][tx * 8 + 4];
#pragma unroll
            for (int i = 0; i < RPT; i++) {
                float a = As[ty * RPT + i][k];
                acc[i][0] += a * b0.x; acc[i][1] += a * b0.y;
                acc[i][2] += a * b0.z; acc[i][3] += a * b0.w;
                acc[i][4] += a * b1.x; acc[i][5] += a * b1.y;
                acc[i][6] += a * b1.z; acc[i][7] += a * b1.w;
            }
        }
        __syncthreads();
    }

    // ---- epilogue + store ----
#pragma unroll
    for (int i = 0; i < RPT; i++) {
        int row = mtile + ty * RPT + i;
        float v[8];
#pragma unroll
        for (int j = 0; j < 8; j++) v[j] = acc[i][j];

        if (EPI == EPI_ELU1) {
#pragma unroll
            for (int j = 0; j < 8; j++) v[j] = (v[j] > 0.f) ? v[j] + 1.f : expf(v[j]);
        } else if (EPI == EPI_RELU) {
#pragma unroll
            for (int j = 0; j < 8; j++) v[j] = fmaxf(v[j], 0.f);
        } else if (EPI == EPI_LN || EPI == EPI_LN_RESID) {
            float s = 0.f;
#pragma unroll
            for (int j = 0; j < 8; j++) s += v[j];
#pragma unroll
            for (int o = 16; o; o >>= 1) s += __shfl_xor_sync(0xffffffffu, s, o);
            float mean = s * (1.f / 256.f);
            float ss = 0.f;
#pragma unroll
            for (int j = 0; j < 8; j++) { float d = v[j] - mean; ss += d * d; }
#pragma unroll
            for (int o = 16; o; o >>= 1) ss += __shfl_xor_sync(0xffffffffu, ss, o);
            float inv = rsqrtf(ss * (1.f / 256.f) + EPS_LN);
#pragma unroll
            for (int j = 0; j < 8; j++) {
                int c = tx * 8 + j;
                float ov = (v[j] - mean) * inv * gamma[c] + beta[c];
                if (EPI == EPI_LN_RESID) ov += resid[(size_t)row * 256 + c];
                v[j] = ov;
            }
        }
        float* crow = C + (size_t)row * Ntot + ncol0 + tx * 8;
        *(float4*)crow       = make_float4(v[0], v[1], v[2], v[3]);
        *(float4*)(crow + 4) = make_float4(v[4], v[5], v[6], v[7]);
    }
}

// ---------------------------------------------------------------------------
// KV = sum_s K^T V (unscaled), Ksum = sum_s K. grid 64 (b,h), 256 thr.
// ---------------------------------------------------------------------------
__global__ void kv_kernel(const float* __restrict__ kmat, const float* __restrict__ vmat,
                          float* __restrict__ kv, float* __restrict__ ksum) {
    __shared__ float Ks[128][32];
    __shared__ float Vs[128][32];
    int bh = blockIdx.x, b = bh >> 3, h = bh & 7;
    int tid = threadIdx.x;
    int d = tid & 31, vg = tid >> 5;
    float acc0 = 0.f, acc1 = 0.f, acc2 = 0.f, acc3 = 0.f, ka = 0.f;

    for (int ch = 0; ch < 2; ch++) {
        int sl = tid >> 3, c4 = tid & 7;
#pragma unroll
        for (int ss = 0; ss < 4; ss++) {
            int srow = ch * 128 + ss * 32 + sl;
            size_t base = ((size_t)(b * 256 + srow)) * 256 + h * 32 + c4 * 4;
            *(float4*)&Ks[ss * 32 + sl][c4 * 4] = *(const float4*)&kmat[base];
            *(float4*)&Vs[ss * 32 + sl][c4 * 4] = *(const float4*)&vmat[base];
        }
        __syncthreads();
#pragma unroll 4
        for (int s = 0; s < 128; s++) {
            float kd = Ks[s][d];
            float4 vv = *(float4*)&Vs[s][vg * 4];
            acc0 += kd * vv.x; acc1 += kd * vv.y;
            acc2 += kd * vv.z; acc3 += kd * vv.w;
            if (vg == 0) ka += kd;
        }
        __syncthreads();
    }
    float* kvp = kv + ((size_t)bh * 32 + d) * 32 + vg * 4;
    kvp[0] = acc0; kvp[1] = acc1; kvp[2] = acc2; kvp[3] = acc3;
    if (vg == 0) ksum[bh * 32 + d] = ka;
}

// ---------------------------------------------------------------------------
// msg = z * (Q @ KV), z = 1/(Q . Ksum + eps). grid (256 token-tiles, 8 b).
// ---------------------------------------------------------------------------
__global__ void attn_apply(const float* __restrict__ qmat, const float* __restrict__ kv,
                           const float* __restrict__ ksum, float* __restrict__ msg) {
    __shared__ float Qs[16 * 256];
    __shared__ float zs[16][8];
    __shared__ float ksums[256];
    int b = blockIdx.y;
    int t0 = blockIdx.x * 16;
    int tid = threadIdx.x;

    const float4* qsrc = (const float4*)(qmat + ((size_t)b * 4096 + t0) * 256);
    float4* qd = (float4*)Qs;
#pragma unroll
    for (int q = 0; q < 4; q++) qd[tid + q * 256] = qsrc[tid + q * 256];
    ksums[tid] = ksum[b * 256 + tid];
    __syncthreads();

    if (tid < 128) {
        int t = tid >> 3, h = tid & 7;
        const float* qrow = Qs + t * 256 + h * 32;
        const float* kr = ksums + h * 32;
        float z = 0.f;
#pragma unroll
        for (int dd = 0; dd < 32; dd++) z += qrow[dd] * kr[dd];
        zs[t][h] = 1.f / (z + EPS_ATT);
    }
    __syncthreads();

    int h = tid >> 5, v = tid & 31;
    float kvr[32];
#pragma unroll
    for (int dd = 0; dd < 32; dd++)
        kvr[dd] = kv[(((size_t)(b * 8 + h)) * 32 + dd) * 32 + v];
#pragma unroll 2
    for (int t = 0; t < 16; t++) {
        const float* qrow = Qs + t * 256 + h * 32;
        float m = 0.f;
#pragma unroll
        for (int dd = 0; dd < 32; dd++) m += qrow[dd] * kvr[dd];
        msg[((size_t)b * 4096 + t0 + t) * 256 + tid] = m * zs[t][h];
    }
}

// ---------------------------------------------------------------------------
// Launch
// ---------------------------------------------------------------------------
extern "C" void kernel_launch(void* const* d_in, const int* in_sizes, int n_in,
                              void* d_out, int out_size) {
    const float* x      = (const float*)d_in[0];
    const float* sr_w   = (const float*)d_in[1];
    const float* sr_b   = (const float*)d_in[2];
    const float* norm_g = (const float*)d_in[3];
    const float* norm_b = (const float*)d_in[4];
    const float* wq     = (const float*)d_in[5];
    const float* wk     = (const float*)d_in[6];
    const float* wv     = (const float*)d_in[7];
    const float* wm     = (const float*)d_in[8];
    const float* w1     = (const float*)d_in[9];
    const float* w2     = (const float*)d_in[10];
    const float* n1g    = (const float*)d_in[11];
    const float* n1b    = (const float*)d_in[12];
    const float* n2g    = (const float*)d_in[13];
    const float* n2b    = (const float*)d_in[14];
    float* out = (float*)d_out;

    float *wsrT, *wqT, *wkT, *wvT, *wmT, *w1T, *w2T;
    float *part, *src, *kmat, *vmat, *kvp, *ksump, *qmat, *msg, *msgn, *hmid;
    cudaGetSymbolAddress((void**)&wsrT, g_wsrT);
    cudaGetSymbolAddress((void**)&wqT,  g_wqT);
    cudaGetSymbolAddress((void**)&wkT,  g_wkT);
    cudaGetSymbolAddress((void**)&wvT,  g_wvT);
    cudaGetSymbolAddress((void**)&wmT,  g_wmT);
    cudaGetSymbolAddress((void**)&w1T,  g_w1T);
    cudaGetSymbolAddress((void**)&w2T,  g_w2T);
    cudaGetSymbolAddress((void**)&part, g_part);
    cudaGetSymbolAddress((void**)&src,  g_src);
    cudaGetSymbolAddress((void**)&kmat, g_kmat);
    cudaGetSymbolAddress((void**)&vmat, g_vmat);
    cudaGetSymbolAddress((void**)&kvp,  g_kv);
    cudaGetSymbolAddress((void**)&ksump,g_ksum);
    cudaGetSymbolAddress((void**)&qmat, g_qmat);
    cudaGetSymbolAddress((void**)&msg,  g_msg);
    cudaGetSymbolAddress((void**)&msgn, g_msgn);
    cudaGetSymbolAddress((void**)&hmid, g_hmid);

    // weight repacks
    repack_srw<<<256, 256>>>(sr_w, wsrT);
    transpose_k<<<dim3(8, 8),  dim3(32, 8)>>>(wq, wqT, 256, 256);
    transpose_k<<<dim3(8, 8),  dim3(32, 8)>>>(wk, wkT, 256, 256);
    transpose_k<<<dim3(8, 8),  dim3(32, 8)>>>(wv, wvT, 256, 256);
    transpose_k<<<dim3(8, 8),  dim3(32, 8)>>>(wm, wmT, 256, 256);
    transpose_k<<<dim3(16,16), dim3(32, 8)>>>(w1, w1T, 512, 512);
    transpose_k<<<dim3(16, 8), dim3(32, 8)>>>(w2, w2T, 256, 512);

    // subsample conv (split-K) + bias + LN
    conv_gemm<<<dim3(128, 4), 256>>>(x, wsrT, part);
    reduce_ln<<<256, 256>>>(part, sr_b, norm_g, norm_b, src);

    // k/v projections (M=2048)
    gemm_bn256<2, EPI_ELU1, false><<<dim3(128, 1), 256>>>(src, nullptr, wkT, kmat, 256, 256, nullptr, nullptr, nullptr);
    gemm_bn256<2, EPI_PLAIN, false><<<dim3(128, 1), 256>>>(src, nullptr, wvT, vmat, 256, 256, nullptr, nullptr, nullptr);

    // KV / Ksum
    kv_kernel<<<64, 256>>>(kmat, vmat, kvp, ksump);

    // q projection (M=32768) -> elu+1
    gemm_bn256<8, EPI_ELU1, false><<<dim3(512, 1), 256>>>(x, nullptr, wqT, qmat, 256, 256, nullptr, nullptr, nullptr);

    // linear attention apply
    attn_apply<<<dim3(256, 8), 256>>>(qmat, kvp, ksump, msg);

    // merge projection + LN1
    gemm_bn256<8, EPI_LN, false><<<dim3(512, 1), 256>>>(msg, nullptr, wmT, msgn, 256, 256, n1g, n1b, nullptr);

    // MLP1: concat(x, msgn) @ w1^T -> relu (N=512 via two column blocks)
    gemm_bn256<8, EPI_RELU, true><<<dim3(512, 2), 256>>>(x, msgn, w1T, hmid, 512, 512, nullptr, nullptr, nullptr);

    // MLP2 + LN2 + residual -> out
    gemm_bn256<8, EPI_LN_RESID, false><<<dim3(512, 1), 256>>>(hmid, nullptr, w2T, out, 512, 256, n2g, n2b, x);
}

// round 3
// speedup vs baseline: 2.9386x; 2.9386x over previous
#include <cuda_runtime.h>
#include <math.h>
#include <stdint.h>

#define EPS_LN  1e-5f
#define EPS_ATT 1e-6f

// ---------------------------------------------------------------------------
// helpers
// ---------------------------------------------------------------------------
__device__ __forceinline__ uint32_t smem_u32(const void* p) {
    uint32_t a;
    asm("{ .reg .u64 t; cvta.to.shared.u64 t, %1; cvt.u32.u64 %0, t; }" : "=r"(a) : "l"(p));
    return a;
}
__device__ __forceinline__ uint32_t f2tf(float x) {
    uint32_t r;
    asm("cvt.rna.tf32.f32 %0, %1;" : "=r"(r) : "f"(x));
    return r;
}
#define CP_ASYNC16(dst, src) \
    asm volatile("cp.async.cg.shared.global [%0], [%1], 16;" :: "r"(dst), "l"(src))
#define CP_COMMIT() asm volatile("cp.async.commit_group;")
#define CP_WAIT1()  asm volatile("cp.async.wait_group 1;" ::: "memory")
#define CP_WAIT0()  asm volatile("cp.async.wait_group 0;" ::: "memory")

__device__ __forceinline__ void mma8(float* c, const uint32_t* a, const uint32_t* b) {
    asm volatile(
        "mma.sync.aligned.m16n8k8.row.col.f32.tf32.tf32.f32 "
        "{%0,%1,%2,%3}, {%4,%5,%6,%7}, {%8,%9}, {%0,%1,%2,%3};"
        : "+f"(c[0]), "+f"(c[1]), "+f"(c[2]), "+f"(c[3])
        : "r"(a[0]), "r"(a[1]), "r"(a[2]), "r"(a[3]), "r"(b[0]), "r"(b[1]));
}

// ---------------------------------------------------------------------------
// Scratch
// ---------------------------------------------------------------------------
__device__ float g_wsrB[256 * 4096];        // conv weight [o][k=rr*256+i]
__device__ float g_part[8 * 2048 * 256];    // conv split-K partials
__device__ float g_src [2048 * 256];
__device__ float g_kmat[2048 * 256];
__device__ float g_vmat[2048 * 256];
__device__ float g_kv  [64 * 32 * 32];
__device__ float g_ksum[64 * 32];
__device__ float g_qmat[8 * 4096 * 256];
__device__ float g_msg [8 * 4096 * 256];
__device__ float g_msgn[8 * 4096 * 256];
__device__ float g_hmid[8 * 4096 * 512];

// sr_w OIHW [o][i][4][4] -> wsrB[o*4096 + rr*256 + i]
__global__ void repack_srw(const float* __restrict__ w, float* __restrict__ wb) {
    int idx = blockIdx.x * blockDim.x + threadIdx.x;   // 65536
    int o = idx >> 8, i = idx & 255;
    const float* p = w + ((size_t)(o * 256 + i)) * 16;
#pragma unroll
    for (int rr = 0; rr < 16; rr++)
        wb[(size_t)o * 4096 + rr * 256 + i] = p[rr];
}

// ---------------------------------------------------------------------------
// Split-K reduce + bias + LayerNorm -> src. grid 256, 256 thr.
// ---------------------------------------------------------------------------
__global__ void reduce_ln(const float* __restrict__ part, const float* __restrict__ bias,
                          const float* __restrict__ g, const float* __restrict__ bb,
                          float* __restrict__ out) {
    int lane = threadIdx.x & 31, w = threadIdx.x >> 5;
    int row = blockIdx.x * 8 + w;
    float v[8];
#pragma unroll
    for (int j = 0; j < 8; j++) {
        int c = lane + j * 32;
        float s = 0.f;
#pragma unroll
        for (int ks = 0; ks < 8; ks++)
            s += part[((size_t)ks * 2048 + row) * 256 + c];
        v[j] = s + bias[c];
    }
    float sum = 0.f;
#pragma unroll
    for (int j = 0; j < 8; j++) sum += v[j];
#pragma unroll
    for (int o = 16; o; o >>= 1) sum += __shfl_xor_sync(0xffffffffu, sum, o);
    float mean = sum * (1.f / 256.f);
    float ss = 0.f;
#pragma unroll
    for (int j = 0; j < 8; j++) { float d = v[j] - mean; ss += d * d; }
#pragma unroll
    for (int o = 16; o; o >>= 1) ss += __shfl_xor_sync(0xffffffffu, ss, o);
    float inv = rsqrtf(ss * (1.f / 256.f) + EPS_LN);
#pragma unroll
    for (int j = 0; j < 8; j++) {
        int c = lane + j * 32;
        out[(size_t)row * 256 + c] = (v[j] - mean) * inv * g[c] + bb[c];
    }
}

// ---------------------------------------------------------------------------
// tf32 mma.sync GEMM. BM=128, BN=256, BK=32, 256 thr, 8 warps (2x4),
// warp tile 64x64. Double-buffered cp.async smem, stride-36 padding.
// MODE: 0=plain A[m][Kloc], 1=concat(A0,A1), 2=conv gather + split-K
// EPI: 0 plain, 1 elu+1, 2 relu, 3 LN, 4 LN+resid
// ---------------------------------------------------------------------------
#define EPI_PLAIN    0
#define EPI_ELU1     1
#define EPI_RELU     2
#define EPI_LN       3
#define EPI_LN_RESID 4

#define ASTRIDE   36
#define STAGE_F   13824            // (128+256)*36 floats
#define AF        4608             // 128*36
#define EPISTRIDE 260
#define SMEM_REQ  134144           // max(2*55296, 128*260*4 + 1024)

template <int EPI, int MODE>
__global__ __launch_bounds__(256, 1)
void mma_gemm(const float* __restrict__ A0, const float* __restrict__ A1,
              const float* __restrict__ Bw, float* __restrict__ C,
              int Kloc, int KB, int Ntot,
              const float* __restrict__ gamma, const float* __restrict__ beta,
              const float* __restrict__ resid) {
    extern __shared__ float dsm[];
    const uint32_t sb = smem_u32(dsm);

    const int tid  = threadIdx.x;
    const int lane = tid & 31;
    const int wid  = tid >> 5;
    const int g    = lane >> 2;      // 0..7
    const int t    = lane & 3;       // 0..3
    const int warp_m = wid & 1;      // 2
    const int warp_n = wid >> 1;     // 4

    const int mtile = blockIdx.x * 128;
    int ncol0, kstart;
    float* Cblk = C;
    if (MODE == 2) { ncol0 = 0; kstart = blockIdx.y * 512; Cblk = C + (size_t)blockIdx.y * 2048 * 256; }
    else           { ncol0 = blockIdx.y * 256; kstart = 0; }
    const int KT = Kloc / 32;

    float acc[4][8][4];
#pragma unroll
    for (int i = 0; i < 4; i++)
#pragma unroll
        for (int j = 0; j < 8; j++)
#pragma unroll
            for (int q = 0; q < 4; q++) acc[i][j][q] = 0.f;

    // ---- async tile loader ----
    auto load_tile = [&](int kt, int s) {
        const int kbase = kstart + kt * 32;
        const uint32_t sA = sb + (uint32_t)s * (STAGE_F * 4);
        const uint32_t sB = sA + AF * 4;
        // A: 128 x 32 -> 4 float4 per thread
#pragma unroll
        for (int p = 0; p < 4; p++) {
            int idx = p * 256 + tid;
            int m = idx >> 3, c = idx & 7;
            int kk = kbase + c * 4;
            const float* gp;
            if (MODE == 2) {
                int mg = mtile + m;
                int b = mg >> 8, s5 = mg & 255;
                int rr = kk >> 8, i = kk & 255;
                int n = (((s5 >> 4) * 4 + (rr >> 2)) << 6) + ((s5 & 15) << 2) + (rr & 3);
                gp = A0 + (((size_t)b << 12) + n) * 256 + i;
            } else if (MODE == 1) {
                gp = (kk < 256) ? (A0 + (size_t)(mtile + m) * 256 + kk)
                                : (A1 + (size_t)(mtile + m) * 256 + (kk - 256));
            } else {
                gp = A0 + (size_t)(mtile + m) * Kloc + kk;
            }
            CP_ASYNC16(sA + (uint32_t)(m * ASTRIDE + c * 4) * 4, gp);
        }
        // B: 256 x 32 -> 8 float4 per thread  (weights native [N][K])
#pragma unroll
        for (int p = 0; p < 8; p++) {
            int idx = p * 256 + tid;
            int n = idx >> 3, c = idx & 7;
            const float* gp = Bw + (size_t)(ncol0 + n) * KB + kbase + c * 4;
            CP_ASYNC16(sB + (uint32_t)(n * ASTRIDE + c * 4) * 4, gp);
        }
        CP_COMMIT();
    };

    // fragment row bases (float offsets)
    int arow[4], brow[8];
#pragma unroll
    for (int mf = 0; mf < 4; mf++) arow[mf] = (warp_m * 64 + mf * 16 + g) * ASTRIDE;
#pragma unroll
    for (int nf = 0; nf < 8; nf++) brow[nf] = (warp_n * 64 + nf * 8 + g) * ASTRIDE;

    load_tile(0, 0);

    for (int kt = 0; kt < KT; kt++) {
        if (kt + 1 < KT) { load_tile(kt + 1, (kt + 1) & 1); CP_WAIT1(); }
        else             { CP_WAIT0(); }
        __syncthreads();

        const float* As = dsm + (kt & 1) * STAGE_F;
        const float* Bs = As + AF;
#pragma unroll
        for (int ks8 = 0; ks8 < 4; ks8++) {
            const int k0 = ks8 * 8 + t;
            uint32_t a[4][4], b[8][2];
#pragma unroll
            for (int mf = 0; mf < 4; mf++) {
                a[mf][0] = f2tf(As[arow[mf] + k0]);
                a[mf][1] = f2tf(As[arow[mf] + 8 * ASTRIDE + k0]);
                a[mf][2] = f2tf(As[arow[mf] + k0 + 4]);
                a[mf][3] = f2tf(As[arow[mf] + 8 * ASTRIDE + k0 + 4]);
            }
#pragma unroll
            for (int nf = 0; nf < 8; nf++) {
                b[nf][0] = f2tf(Bs[brow[nf] + k0]);
                b[nf][1] = f2tf(Bs[brow[nf] + k0 + 4]);
            }
#pragma unroll
            for (int mf = 0; mf < 4; mf++)
#pragma unroll
                for (int nf = 0; nf < 8; nf++)
                    mma8(acc[mf][nf], a[mf], b[nf]);
        }
        __syncthreads();
    }

    // ---- epilogue: stage accumulators to smem ----
    float* sepi   = dsm;
    float* s_mean = dsm + 33280;
    float* s_inv  = dsm + 33408;

#pragma unroll
    for (int mf = 0; mf < 4; mf++) {
        int r0 = warp_m * 64 + mf * 16 + g;
#pragma unroll
        for (int nf = 0; nf < 8; nf++) {
            int c0 = warp_n * 64 + nf * 8 + 2 * t;
            float v0 = acc[mf][nf][0], v1 = acc[mf][nf][1];
            float v2 = acc[mf][nf][2], v3 = acc[mf][nf][3];
            if (EPI == EPI_ELU1) {
                v0 = (v0 > 0.f) ? v0 + 1.f : __expf(v0);
                v1 = (v1 > 0.f) ? v1 + 1.f : __expf(v1);
                v2 = (v2 > 0.f) ? v2 + 1.f : __expf(v2);
                v3 = (v3 > 0.f) ? v3 + 1.f : __expf(v3);
            }
            if (EPI == EPI_RELU) {
                v0 = fmaxf(v0, 0.f); v1 = fmaxf(v1, 0.f);
                v2 = fmaxf(v2, 0.f); v3 = fmaxf(v3, 0.f);
            }
            *(float2*)&sepi[r0 * EPISTRIDE + c0]       = make_float2(v0, v1);
            *(float2*)&sepi[(r0 + 8) * EPISTRIDE + c0] = make_float2(v2, v3);
        }
    }
    __syncthreads();

    if ((EPI == EPI_LN || EPI == EPI_LN_RESID) && tid < 128) {
        const float* rowp = sepi + tid * EPISTRIDE;
        float sum = 0.f, ss = 0.f;
#pragma unroll 8
        for (int j = 0; j < 64; j++) {
            float4 v = *(const float4*)&rowp[j * 4];
            sum += v.x + v.y + v.z + v.w;
            ss  += v.x * v.x + v.y * v.y + v.z * v.z + v.w * v.w;
        }
        float mean = sum * (1.f / 256.f);
        float var  = ss * (1.f / 256.f) - mean * mean;
        s_mean[tid] = mean;
        s_inv[tid]  = rsqrtf(var + EPS_LN);
    }
    if (EPI == EPI_LN || EPI == EPI_LN_RESID) __syncthreads();

    // coalesced store (+ LN transform / residual)
#pragma unroll 4
    for (int p = 0; p < 32; p++) {
        int idx4 = p * 256 + tid;
        int row = idx4 >> 6;
        int c4  = (idx4 & 63) << 2;
        float4 v = *(const float4*)&sepi[row * EPISTRIDE + c4];
        if (EPI == EPI_LN || EPI == EPI_LN_RESID) {
            float m = s_mean[row], iv = s_inv[row];
            float4 gm = *(const float4*)&gamma[c4];
            float4 bt = *(const float4*)&beta[c4];
            v.x = (v.x - m) * iv * gm.x + bt.x;
            v.y = (v.y - m) * iv * gm.y + bt.y;
            v.z = (v.z - m) * iv * gm.z + bt.z;
            v.w = (v.w - m) * iv * gm.w + bt.w;
            if (EPI == EPI_LN_RESID) {
                float4 r = *(const float4*)&resid[(size_t)(mtile + row) * 256 + c4];
                v.x += r.x; v.y += r.y; v.z += r.z; v.w += r.w;
            }
        }
        *(float4*)&Cblk[(size_t)(mtile + row) * Ntot + ncol0 + c4] = v;
    }
}

// ---------------------------------------------------------------------------
// KV = sum_s K^T V, Ksum = sum_s K. grid 64, 256 thr.
// ---------------------------------------------------------------------------
__global__ void kv_kernel(const float* __restrict__ kmat, const float* __restrict__ vmat,
                          float* __restrict__ kv, float* __restrict__ ksum) {
    __shared__ float Ks[128][32];
    __shared__ float Vs[128][32];
    int bh = blockIdx.x, b = bh >> 3, h = bh & 7;
    int tid = threadIdx.x;
    int d = tid & 31, vg = tid >> 5;
    float acc0 = 0.f, acc1 = 0.f, acc2 = 0.f, acc3 = 0.f, ka = 0.f;

    for (int ch = 0; ch < 2; ch++) {
        int sl = tid >> 3, c4 = tid & 7;
#pragma unroll
        for (int ss = 0; ss < 4; ss++) {
            int srow = ch * 128 + ss * 32 + sl;
            size_t base = ((size_t)(b * 256 + srow)) * 256 + h * 32 + c4 * 4;
            *(float4*)&Ks[ss * 32 + sl][c4 * 4] = *(const float4*)&kmat[base];
            *(float4*)&Vs[ss * 32 + sl][c4 * 4] = *(const float4*)&vmat[base];
        }
        __syncthreads();
#pragma unroll 4
        for (int s = 0; s < 128; s++) {
            float kd = Ks[s][d];
            float4 vv = *(float4*)&Vs[s][vg * 4];
            acc0 += kd * vv.x; acc1 += kd * vv.y;
            acc2 += kd * vv.z; acc3 += kd * vv.w;
            if (vg == 0) ka += kd;
        }
        __syncthreads();
    }
    float* kvp = kv + ((size_t)bh * 32 + d) * 32 + vg * 4;
    kvp[0] = acc0; kvp[1] = acc1; kvp[2] = acc2; kvp[3] = acc3;
    if (vg == 0) ksum[bh * 32 + d] = ka;
}

// ---------------------------------------------------------------------------
// msg = z * (Q @ KV), z = 1/(Q.Ksum + eps). grid (256, 8).
// ---------------------------------------------------------------------------
__global__ void attn_apply(const float* __restrict__ qmat, const float* __restrict__ kv,
                           const float* __restrict__ ksum, float* __restrict__ msg) {
    __shared__ float Qs[16 * 256];
    __shared__ float zs[16][8];
    __shared__ float ksums[256];
    int b = blockIdx.y;
    int t0 = blockIdx.x * 16;
    int tid = threadIdx.x;

    const float4* qsrc = (const float4*)(qmat + ((size_t)b * 4096 + t0) * 256);
    float4* qd = (float4*)Qs;
#pragma unroll
    for (int q = 0; q < 4; q++) qd[tid + q * 256] = qsrc[tid + q * 256];
    ksums[tid] = ksum[b * 256 + tid];
    __syncthreads();

    if (tid < 128) {
        int t = tid >> 3, h = tid & 7;
        const float* qrow = Qs + t * 256 + h * 32;
        const float* kr = ksums + h * 32;
        float z = 0.f;
#pragma unroll
        for (int dd = 0; dd < 32; dd++) z += qrow[dd] * kr[dd];
        zs[t][h] = 1.f / (z + EPS_ATT);
    }
    __syncthreads();

    int h = tid >> 5, v = tid & 31;
    float kvr[32];
#pragma unroll
    for (int dd = 0; dd < 32; dd++)
        kvr[dd] = kv[(((size_t)(b * 8 + h)) * 32 + dd) * 32 + v];
#pragma unroll 2
    for (int t = 0; t < 16; t++) {
        const float* qrow = Qs + t * 256 + h * 32;
        float m = 0.f;
#pragma unroll
        for (int dd = 0; dd < 32; dd++) m += qrow[dd] * kvr[dd];
        msg[((size_t)b * 4096 + t0 + t) * 256 + tid] = m * zs[t][h];
    }
}

// ---------------------------------------------------------------------------
// Launch
// ---------------------------------------------------------------------------
extern "C" void kernel_launch(void* const* d_in, const int* in_sizes, int n_in,
                              void* d_out, int out_size) {
    const float* x      = (const float*)d_in[0];
    const float* sr_w   = (const float*)d_in[1];
    const float* sr_b   = (const float*)d_in[2];
    const float* norm_g = (const float*)d_in[3];
    const float* norm_b = (const float*)d_in[4];
    const float* wq     = (const float*)d_in[5];
    const float* wk     = (const float*)d_in[6];
    const float* wv     = (const float*)d_in[7];
    const float* wm     = (const float*)d_in[8];
    const float* w1     = (const float*)d_in[9];
    const float* w2     = (const float*)d_in[10];
    const float* n1g    = (const float*)d_in[11];
    const float* n1b    = (const float*)d_in[12];
    const float* n2g    = (const float*)d_in[13];
    const float* n2b    = (const float*)d_in[14];
    float* out = (float*)d_out;

    float *wsrB, *part, *src, *kmat, *vmat, *kvp, *ksump, *qmat, *msg, *msgn, *hmid;
    cudaGetSymbolAddress((void**)&wsrB, g_wsrB);
    cudaGetSymbolAddress((void**)&part, g_part);
    cudaGetSymbolAddress((void**)&src,  g_src);
    cudaGetSymbolAddress((void**)&kmat, g_kmat);
    cudaGetSymbolAddress((void**)&vmat, g_vmat);
    cudaGetSymbolAddress((void**)&kvp,  g_kv);
    cudaGetSymbolAddress((void**)&ksump,g_ksum);
    cudaGetSymbolAddress((void**)&qmat, g_qmat);
    cudaGetSymbolAddress((void**)&msg,  g_msg);
    cudaGetSymbolAddress((void**)&msgn, g_msgn);
    cudaGetSymbolAddress((void**)&hmid, g_hmid);

    cudaFuncSetAttribute(mma_gemm<EPI_PLAIN, 2>,    cudaFuncAttributeMaxDynamicSharedMemorySize, SMEM_REQ);
    cudaFuncSetAttribute(mma_gemm<EPI_ELU1, 0>,     cudaFuncAttributeMaxDynamicSharedMemorySize, SMEM_REQ);
    cudaFuncSetAttribute(mma_gemm<EPI_PLAIN, 0>,    cudaFuncAttributeMaxDynamicSharedMemorySize, SMEM_REQ);
    cudaFuncSetAttribute(mma_gemm<EPI_LN, 0>,       cudaFuncAttributeMaxDynamicSharedMemorySize, SMEM_REQ);
    cudaFuncSetAttribute(mma_gemm<EPI_RELU, 1>,     cudaFuncAttributeMaxDynamicSharedMemorySize, SMEM_REQ);
    cudaFuncSetAttribute(mma_gemm<EPI_LN_RESID, 0>, cudaFuncAttributeMaxDynamicSharedMemorySize, SMEM_REQ);

    // conv weight repack, conv-as-GEMM (split-K=8) + reduce/bias/LN
    repack_srw<<<256, 256>>>(sr_w, wsrB);
    mma_gemm<EPI_PLAIN, 2><<<dim3(16, 8), 256, SMEM_REQ>>>(
        x, nullptr, wsrB, part, 512, 4096, 256, nullptr, nullptr, nullptr);
    reduce_ln<<<256, 256>>>(part, sr_b, norm_g, norm_b, src);

    // k/v projections (M=2048), weights in native [N][K]
    mma_gemm<EPI_ELU1, 0><<<dim3(16, 1), 256, SMEM_REQ>>>(
        src, nullptr, wk, kmat, 256, 256, 256, nullptr, nullptr, nullptr);
    mma_gemm<EPI_PLAIN, 0><<<dim3(16, 1), 256, SMEM_REQ>>>(
        src, nullptr, wv, vmat, 256, 256, 256, nullptr, nullptr, nullptr);

    kv_kernel<<<64, 256>>>(kmat, vmat, kvp, ksump);

    // q projection (M=32768) -> elu+1
    mma_gemm<EPI_ELU1, 0><<<dim3(256, 1), 256, SMEM_REQ>>>(
        x, nullptr, wq, qmat, 256, 256, 256, nullptr, nullptr, nullptr);

    attn_apply<<<dim3(256, 8), 256>>>(qmat, kvp, ksump, msg);

    // merge projection + LN1
    mma_gemm<EPI_LN, 0><<<dim3(256, 1), 256, SMEM_REQ>>>(
        msg, nullptr, wm, msgn, 256, 256, 256, n1g, n1b, nullptr);

    // MLP1: concat(x, msgn) @ w1^T -> relu (Ntot=512, 2 column blocks)
    mma_gemm<EPI_RELU, 1><<<dim3(256, 2), 256, SMEM_REQ>>>(
        x, msgn, w1, hmid, 512, 512, 512, nullptr, nullptr, nullptr);

    // MLP2 + LN2 + residual -> out
    mma_gemm<EPI_LN_RESID, 0><<<dim3(256, 1), 256, SMEM_REQ>>>(
        hmid, nullptr, w2, out, 512, 512, 256, n2g, n2b, x);
}

// round 4
// speedup vs baseline: 3.0718x; 1.0453x over previous
#include <cuda_runtime.h>
#include <math.h>
#include <stdint.h>

#define EPS_LN  1e-5f
#define EPS_ATT 1e-6f

// ---------------------------------------------------------------------------
// helpers
// ---------------------------------------------------------------------------
__device__ __forceinline__ uint32_t smem_u32(const void* p) {
    uint32_t a;
    asm("{ .reg .u64 t; cvta.to.shared.u64 t, %1; cvt.u32.u64 %0, t; }" : "=r"(a) : "l"(p));
    return a;
}
__device__ __forceinline__ uint32_t f2tf(float x) {
    uint32_t r;
    asm("cvt.rna.tf32.f32 %0, %1;" : "=r"(r) : "f"(x));
    return r;
}
#define CP_ASYNC16(dst, src) \
    asm volatile("cp.async.cg.shared.global [%0], [%1], 16;" :: "r"(dst), "l"(src))
#define CP_COMMIT() asm volatile("cp.async.commit_group;")
#define CP_WAIT1()  asm volatile("cp.async.wait_group 1;" ::: "memory")
#define CP_WAIT0()  asm volatile("cp.async.wait_group 0;" ::: "memory")

__device__ __forceinline__ void mma8(float* c, const uint32_t* a, const uint32_t* b) {
    asm volatile(
        "mma.sync.aligned.m16n8k8.row.col.f32.tf32.tf32.f32 "
        "{%0,%1,%2,%3}, {%4,%5,%6,%7}, {%8,%9}, {%0,%1,%2,%3};"
        : "+f"(c[0]), "+f"(c[1]), "+f"(c[2]), "+f"(c[3])
        : "r"(a[0]), "r"(a[1]), "r"(a[2]), "r"(a[3]), "r"(b[0]), "r"(b[1]));
}

// ---------------------------------------------------------------------------
// Scratch
// ---------------------------------------------------------------------------
__device__ float g_wsrB[256 * 4096];        // conv weight [o][k=rr*256+i]
__device__ float g_part[8 * 2048 * 256];    // conv split-K partials
__device__ float g_src [2048 * 256];
__device__ float g_kmat[2048 * 256];
__device__ float g_vmat[2048 * 256];
__device__ float g_kv  [64 * 32 * 32];
__device__ float g_ksum[64 * 32];
__device__ float g_qmat[8 * 4096 * 256];
__device__ float g_msg [8 * 4096 * 256];
__device__ float g_msgn[8 * 4096 * 256];
__device__ float g_hmid[8 * 4096 * 512];

// sr_w OIHW [o][i][4][4] -> wsrB[o*4096 + rr*256 + i]
__global__ void repack_srw(const float* __restrict__ w, float* __restrict__ wb) {
    int idx = blockIdx.x * blockDim.x + threadIdx.x;   // 65536
    int o = idx >> 8, i = idx & 255;
    const float* p = w + ((size_t)(o * 256 + i)) * 16;
#pragma unroll
    for (int rr = 0; rr < 16; rr++)
        wb[(size_t)o * 4096 + rr * 256 + i] = p[rr];
}

// ---------------------------------------------------------------------------
// Split-K reduce + bias + LayerNorm -> src. grid 256, 256 thr.
// ---------------------------------------------------------------------------
__global__ void reduce_ln(const float* __restrict__ part, const float* __restrict__ bias,
                          const float* __restrict__ g, const float* __restrict__ bb,
                          float* __restrict__ out) {
    int lane = threadIdx.x & 31, w = threadIdx.x >> 5;
    int row = blockIdx.x * 8 + w;
    float v[8];
#pragma unroll
    for (int j = 0; j < 8; j++) {
        int c = lane + j * 32;
        float s = 0.f;
#pragma unroll
        for (int ks = 0; ks < 8; ks++)
            s += part[((size_t)ks * 2048 + row) * 256 + c];
        v[j] = s + bias[c];
    }
    float sum = 0.f;
#pragma unroll
    for (int j = 0; j < 8; j++) sum += v[j];
#pragma unroll
    for (int o = 16; o; o >>= 1) sum += __shfl_xor_sync(0xffffffffu, sum, o);
    float mean = sum * (1.f / 256.f);
    float ss = 0.f;
#pragma unroll
    for (int j = 0; j < 8; j++) { float d = v[j] - mean; ss += d * d; }
#pragma unroll
    for (int o = 16; o; o >>= 1) ss += __shfl_xor_sync(0xffffffffu, ss, o);
    float inv = rsqrtf(ss * (1.f / 256.f) + EPS_LN);
#pragma unroll
    for (int j = 0; j < 8; j++) {
        int c = lane + j * 32;
        out[(size_t)row * 256 + c] = (v[j] - mean) * inv * g[c] + bb[c];
    }
}

// ---------------------------------------------------------------------------
// tf32 mma.sync GEMM. BM=128, BN=256, BK=32, 256 thr, 8 warps (2x4),
// warp tile 64x64. 3-stage cp.async pipeline, ONE sync per stage.
// MODE: 0=plain A[m][Kloc], 1=concat(A0,A1), 2=conv gather + split-K,
//       3=fused k/v (blockIdx.y: 0 -> Bw/elu -> C, 1 -> Bw2/plain -> C2)
// EPI: 0 plain, 1 elu+1, 2 relu, 3 LN, 4 LN+resid
// ---------------------------------------------------------------------------
#define EPI_PLAIN    0
#define EPI_ELU1     1
#define EPI_RELU     2
#define EPI_LN       3
#define EPI_LN_RESID 4

#define ASTRIDE   36
#define STAGE_F   13824            // (128+256)*36 floats
#define AF        4608             // 128*36
#define EPISTRIDE 260
#define SMEM_REQ  165888           // 3 stages * 13824 * 4B

template <int EPI, int MODE>
__global__ __launch_bounds__(256, 1)
void mma_gemm(const float* __restrict__ A0, const float* __restrict__ A1,
              const float* __restrict__ Bw, float* __restrict__ C,
              int Kloc, int KB, int Ntot,
              const float* __restrict__ gamma, const float* __restrict__ beta,
              const float* __restrict__ resid,
              const float* __restrict__ Bw2, float* __restrict__ C2) {
    extern __shared__ float dsm[];
    const uint32_t sb = smem_u32(dsm);

    const int tid  = threadIdx.x;
    const int lane = tid & 31;
    const int wid  = tid >> 5;
    const int g    = lane >> 2;      // 0..7
    const int t    = lane & 3;       // 0..3
    const int warp_m = wid & 1;      // 2
    const int warp_n = wid >> 1;     // 4

    const int mtile = blockIdx.x * 128;
    int ncol0, kstart;
    float* Cblk = C;
    const float* Bsrc = Bw;
    if (MODE == 2) { ncol0 = 0; kstart = blockIdx.y * 512; Cblk = C + (size_t)blockIdx.y * 2048 * 256; }
    else if (MODE == 3) { ncol0 = 0; kstart = 0; if (blockIdx.y) { Bsrc = Bw2; Cblk = C2; } }
    else { ncol0 = blockIdx.y * 256; kstart = 0; }
    const int KT = Kloc / 32;

    float acc[4][8][4];
#pragma unroll
    for (int i = 0; i < 4; i++)
#pragma unroll
        for (int j = 0; j < 8; j++)
#pragma unroll
            for (int q = 0; q < 4; q++) acc[i][j][q] = 0.f;

    // ---- async tile loader (commits one group) ----
    auto load_tile = [&](int kt, int s) {
        const int kbase = kstart + kt * 32;
        const uint32_t sA = sb + (uint32_t)s * (STAGE_F * 4);
        const uint32_t sB = sA + AF * 4;
#pragma unroll
        for (int p = 0; p < 4; p++) {
            int idx = p * 256 + tid;
            int m = idx >> 3, c = idx & 7;
            int kk = kbase + c * 4;
            const float* gp;
            if (MODE == 2) {
                int mg = mtile + m;
                int b = mg >> 8, s5 = mg & 255;
                int rr = kk >> 8, i = kk & 255;
                int n = (((s5 >> 4) * 4 + (rr >> 2)) << 6) + ((s5 & 15) << 2) + (rr & 3);
                gp = A0 + (((size_t)b << 12) + n) * 256 + i;
            } else if (MODE == 1) {
                gp = (kk < 256) ? (A0 + (size_t)(mtile + m) * 256 + kk)
                                : (A1 + (size_t)(mtile + m) * 256 + (kk - 256));
            } else {
                gp = A0 + (size_t)(mtile + m) * Kloc + kk;
            }
            CP_ASYNC16(sA + (uint32_t)(m * ASTRIDE + c * 4) * 4, gp);
        }
#pragma unroll
        for (int p = 0; p < 8; p++) {
            int idx = p * 256 + tid;
            int n = idx >> 3, c = idx & 7;
            const float* gp = Bsrc + (size_t)(ncol0 + n) * KB + kbase + c * 4;
            CP_ASYNC16(sB + (uint32_t)(n * ASTRIDE + c * 4) * 4, gp);
        }
        CP_COMMIT();
    };

    int arow[4], brow[8];
#pragma unroll
    for (int mf = 0; mf < 4; mf++) arow[mf] = (warp_m * 64 + mf * 16 + g) * ASTRIDE;
#pragma unroll
    for (int nf = 0; nf < 8; nf++) brow[nf] = (warp_n * 64 + nf * 8 + g) * ASTRIDE;

    // prologue: fill 2 of 3 stages
    load_tile(0, 0);
    if (KT > 1) load_tile(1, 1);

    for (int kt = 0; kt < KT; kt++) {
        if (kt + 1 < KT) { CP_WAIT1(); } else { CP_WAIT0(); }
        __syncthreads();
        if (kt + 2 < KT) load_tile(kt + 2, (kt + 2) % 3);

        const float* As = dsm + (kt % 3) * STAGE_F;
        const float* Bs = As + AF;
#pragma unroll
        for (int ks8 = 0; ks8 < 4; ks8++) {
            const int k0 = ks8 * 8 + t;
            uint32_t a[4][4], b[8][2];
#pragma unroll
            for (int mf = 0; mf < 4; mf++) {
                a[mf][0] = f2tf(As[arow[mf] + k0]);
                a[mf][1] = f2tf(As[arow[mf] + 8 * ASTRIDE + k0]);
                a[mf][2] = f2tf(As[arow[mf] + k0 + 4]);
                a[mf][3] = f2tf(As[arow[mf] + 8 * ASTRIDE + k0 + 4]);
            }
#pragma unroll
            for (int nf = 0; nf < 8; nf++) {
                b[nf][0] = f2tf(Bs[brow[nf] + k0]);
                b[nf][1] = f2tf(Bs[brow[nf] + k0 + 4]);
            }
#pragma unroll
            for (int mf = 0; mf < 4; mf++)
#pragma unroll
                for (int nf = 0; nf < 8; nf++)
                    mma8(acc[mf][nf], a[mf], b[nf]);
        }
    }
    __syncthreads();

    // ---- epilogue: stage accumulators to smem ----
    float* sepi   = dsm;
    float* s_mean = dsm + 33280;
    float* s_inv  = dsm + 33408;
    const bool doAct = (MODE != 3) || (blockIdx.y == 0);

#pragma unroll
    for (int mf = 0; mf < 4; mf++) {
        int r0 = warp_m * 64 + mf * 16 + g;
#pragma unroll
        for (int nf = 0; nf < 8; nf++) {
            int c0 = warp_n * 64 + nf * 8 + 2 * t;
            float v0 = acc[mf][nf][0], v1 = acc[mf][nf][1];
            float v2 = acc[mf][nf][2], v3 = acc[mf][nf][3];
            if (EPI == EPI_ELU1 && doAct) {
                v0 = (v0 > 0.f) ? v0 + 1.f : __expf(v0);
                v1 = (v1 > 0.f) ? v1 + 1.f : __expf(v1);
                v2 = (v2 > 0.f) ? v2 + 1.f : __expf(v2);
                v3 = (v3 > 0.f) ? v3 + 1.f : __expf(v3);
            }
            if (EPI == EPI_RELU) {
                v0 = fmaxf(v0, 0.f); v1 = fmaxf(v1, 0.f);
                v2 = fmaxf(v2, 0.f); v3 = fmaxf(v3, 0.f);
            }
            *(float2*)&sepi[r0 * EPISTRIDE + c0]       = make_float2(v0, v1);
            *(float2*)&sepi[(r0 + 8) * EPISTRIDE + c0] = make_float2(v2, v3);
        }
    }
    __syncthreads();

    if ((EPI == EPI_LN || EPI == EPI_LN_RESID) && tid < 128) {
        const float* rowp = sepi + tid * EPISTRIDE;
        float sum = 0.f, ss = 0.f;
#pragma unroll 8
        for (int j = 0; j < 64; j++) {
            float4 v = *(const float4*)&rowp[j * 4];
            sum += v.x + v.y + v.z + v.w;
            ss  += v.x * v.x + v.y * v.y + v.z * v.z + v.w * v.w;
        }
        float mean = sum * (1.f / 256.f);
        float var  = ss * (1.f / 256.f) - mean * mean;
        s_mean[tid] = mean;
        s_inv[tid]  = rsqrtf(var + EPS_LN);
    }
    if (EPI == EPI_LN || EPI == EPI_LN_RESID) __syncthreads();

#pragma unroll 4
    for (int p = 0; p < 32; p++) {
        int idx4 = p * 256 + tid;
        int row = idx4 >> 6;
        int c4  = (idx4 & 63) << 2;
        float4 v = *(const float4*)&sepi[row * EPISTRIDE + c4];
        if (EPI == EPI_LN || EPI == EPI_LN_RESID) {
            float m = s_mean[row], iv = s_inv[row];
            float4 gm = *(const float4*)&gamma[c4];
            float4 bt = *(const float4*)&beta[c4];
            v.x = (v.x - m) * iv * gm.x + bt.x;
            v.y = (v.y - m) * iv * gm.y + bt.y;
            v.z = (v.z - m) * iv * gm.z + bt.z;
            v.w = (v.w - m) * iv * gm.w + bt.w;
            if (EPI == EPI_LN_RESID) {
                float4 r = *(const float4*)&resid[(size_t)(mtile + row) * 256 + c4];
                v.x += r.x; v.y += r.y; v.z += r.z; v.w += r.w;
            }
        }
        *(float4*)&Cblk[(size_t)(mtile + row) * Ntot + ncol0 + c4] = v;
    }
}

// ---------------------------------------------------------------------------
// KV = sum_s K^T V, Ksum = sum_s K. grid 64, 256 thr.
// ---------------------------------------------------------------------------
__global__ void kv_kernel(const float* __restrict__ kmat, const float* __restrict__ vmat,
                          float* __restrict__ kv, float* __restrict__ ksum) {
    __shared__ float Ks[128][32];
    __shared__ float Vs[128][32];
    int bh = blockIdx.x, b = bh >> 3, h = bh & 7;
    int tid = threadIdx.x;
    int d = tid & 31, vg = tid >> 5;
    float acc0 = 0.f, acc1 = 0.f, acc2 = 0.f, acc3 = 0.f, ka = 0.f;

    for (int ch = 0; ch < 2; ch++) {
        int sl = tid >> 3, c4 = tid & 7;
#pragma unroll
        for (int ss = 0; ss < 4; ss++) {
            int srow = ch * 128 + ss * 32 + sl;
            size_t base = ((size_t)(b * 256 + srow)) * 256 + h * 32 + c4 * 4;
            *(float4*)&Ks[ss * 32 + sl][c4 * 4] = *(const float4*)&kmat[base];
            *(float4*)&Vs[ss * 32 + sl][c4 * 4] = *(const float4*)&vmat[base];
        }
        __syncthreads();
#pragma unroll 4
        for (int s = 0; s < 128; s++) {
            float kd = Ks[s][d];
            float4 vv = *(float4*)&Vs[s][vg * 4];
            acc0 += kd * vv.x; acc1 += kd * vv.y;
            acc2 += kd * vv.z; acc3 += kd * vv.w;
            if (vg == 0) ka += kd;
        }
        __syncthreads();
    }
    float* kvp = kv + ((size_t)bh * 32 + d) * 32 + vg * 4;
    kvp[0] = acc0; kvp[1] = acc1; kvp[2] = acc2; kvp[3] = acc3;
    if (vg == 0) ksum[bh * 32 + d] = ka;
}

// ---------------------------------------------------------------------------
// msg = z * (Q @ KV), z = 1/(Q.Ksum + eps). grid (256, 8).
// ---------------------------------------------------------------------------
__global__ void attn_apply(const float* __restrict__ qmat, const float* __restrict__ kv,
                           const float* __restrict__ ksum, float* __restrict__ msg) {
    __shared__ float Qs[16 * 256];
    __shared__ float zs[16][8];
    __shared__ float ksums[256];
    int b = blockIdx.y;
    int t0 = blockIdx.x * 16;
    int tid = threadIdx.x;

    const float4* qsrc = (const float4*)(qmat + ((size_t)b * 4096 + t0) * 256);
    float4* qd = (float4*)Qs;
#pragma unroll
    for (int q = 0; q < 4; q++) qd[tid + q * 256] = qsrc[tid + q * 256];
    ksums[tid] = ksum[b * 256 + tid];
    __syncthreads();

    if (tid < 128) {
        int t = tid >> 3, h = tid & 7;
        const float* qrow = Qs + t * 256 + h * 32;
        const float* kr = ksums + h * 32;
        float z = 0.f;
#pragma unroll
        for (int dd = 0; dd < 32; dd++) z += qrow[dd] * kr[dd];
        zs[t][h] = 1.f / (z + EPS_ATT);
    }
    __syncthreads();

    int h = tid >> 5, v = tid & 31;
    float kvr[32];
#pragma unroll
    for (int dd = 0; dd < 32; dd++)
        kvr[dd] = kv[(((size_t)(b * 8 + h)) * 32 + dd) * 32 + v];
#pragma unroll 2
    for (int t = 0; t < 16; t++) {
        const float* qrow = Qs + t * 256 + h * 32;
        float m = 0.f;
#pragma unroll
        for (int dd = 0; dd < 32; dd++) m += qrow[dd] * kvr[dd];
        msg[((size_t)b * 4096 + t0 + t) * 256 + tid] = m * zs[t][h];
    }
}

// ---------------------------------------------------------------------------
// Launch
// ---------------------------------------------------------------------------
extern "C" void kernel_launch(void* const* d_in, const int* in_sizes, int n_in,
                              void* d_out, int out_size) {
    const float* x      = (const float*)d_in[0];
    const float* sr_w   = (const float*)d_in[1];
    const float* sr_b   = (const float*)d_in[2];
    const float* norm_g = (const float*)d_in[3];
    const float* norm_b = (const float*)d_in[4];
    const float* wq     = (const float*)d_in[5];
    const float* wk     = (const float*)d_in[6];
    const float* wv     = (const float*)d_in[7];
    const float* wm     = (const float*)d_in[8];
    const float* w1     = (const float*)d_in[9];
    const float* w2     = (const float*)d_in[10];
    const float* n1g    = (const float*)d_in[11];
    const float* n1b    = (const float*)d_in[12];
    const float* n2g    = (const float*)d_in[13];
    const float* n2b    = (const float*)d_in[14];
    float* out = (float*)d_out;

    float *wsrB, *part, *src, *kmat, *vmat, *kvp, *ksump, *qmat, *msg, *msgn, *hmid;
    cudaGetSymbolAddress((void**)&wsrB, g_wsrB);
    cudaGetSymbolAddress((void**)&part, g_part);
    cudaGetSymbolAddress((void**)&src,  g_src);
    cudaGetSymbolAddress((void**)&kmat, g_kmat);
    cudaGetSymbolAddress((void**)&vmat, g_vmat);
    cudaGetSymbolAddress((void**)&kvp,  g_kv);
    cudaGetSymbolAddress((void**)&ksump,g_ksum);
    cudaGetSymbolAddress((void**)&qmat, g_qmat);
    cudaGetSymbolAddress((void**)&msg,  g_msg);
    cudaGetSymbolAddress((void**)&msgn, g_msgn);
    cudaGetSymbolAddress((void**)&hmid, g_hmid);

    cudaFuncSetAttribute(mma_gemm<EPI_PLAIN, 2>,    cudaFuncAttributeMaxDynamicSharedMemorySize, SMEM_REQ);
    cudaFuncSetAttribute(mma_gemm<EPI_ELU1, 3>,     cudaFuncAttributeMaxDynamicSharedMemorySize, SMEM_REQ);
    cudaFuncSetAttribute(mma_gemm<EPI_ELU1, 0>,     cudaFuncAttributeMaxDynamicSharedMemorySize, SMEM_REQ);
    cudaFuncSetAttribute(mma_gemm<EPI_LN, 0>,       cudaFuncAttributeMaxDynamicSharedMemorySize, SMEM_REQ);
    cudaFuncSetAttribute(mma_gemm<EPI_RELU, 1>,     cudaFuncAttributeMaxDynamicSharedMemorySize, SMEM_REQ);
    cudaFuncSetAttribute(mma_gemm<EPI_LN_RESID, 0>, cudaFuncAttributeMaxDynamicSharedMemorySize, SMEM_REQ);

    // conv weight repack, conv-as-GEMM (split-K=8) + reduce/bias/LN
    repack_srw<<<256, 256>>>(sr_w, wsrB);
    mma_gemm<EPI_PLAIN, 2><<<dim3(16, 8), 256, SMEM_REQ>>>(
        x, nullptr, wsrB, part, 512, 4096, 256, nullptr, nullptr, nullptr, nullptr, nullptr);
    reduce_ln<<<256, 256>>>(part, sr_b, norm_g, norm_b, src);

    // fused k/v projections (M=2048): y=0 -> wk+elu -> kmat, y=1 -> wv -> vmat
    mma_gemm<EPI_ELU1, 3><<<dim3(16, 2), 256, SMEM_REQ>>>(
        src, nullptr, wk, kmat, 256, 256, 256, nullptr, nullptr, nullptr, wv, vmat);

    kv_kernel<<<64, 256>>>(kmat, vmat, kvp, ksump);

    // q projection (M=32768) -> elu+1
    mma_gemm<EPI_ELU1, 0><<<dim3(256, 1), 256, SMEM_REQ>>>(
        x, nullptr, wq, qmat, 256, 256, 256, nullptr, nullptr, nullptr, nullptr, nullptr);

    attn_apply<<<dim3(256, 8), 256>>>(qmat, kvp, ksump, msg);

    // merge projection + LN1
    mma_gemm<EPI_LN, 0><<<dim3(256, 1), 256, SMEM_REQ>>>(
        msg, nullptr, wm, msgn, 256, 256, 256, n1g, n1b, nullptr, nullptr, nullptr);

    // MLP1: concat(x, msgn) @ w1^T -> relu (Ntot=512, 2 column blocks)
    mma_gemm<EPI_RELU, 1><<<dim3(256, 2), 256, SMEM_REQ>>>(
        x, msgn, w1, hmid, 512, 512, 512, nullptr, nullptr, nullptr, nullptr, nullptr);

    // MLP2 + LN2 + residual -> out
    mma_gemm<EPI_LN_RESID, 0><<<dim3(256, 1), 256, SMEM_REQ>>>(
        hmid, nullptr, w2, out, 512, 512, 256, n2g, n2b, x, nullptr, nullptr);
}